// round 16
// baseline (speedup 1.0000x reference)
#include <cuda_runtime.h>

#define NPTS 50176
#define BATCH 64
#define KC 16
#define CAP 192

// -------- scratch (static device memory; no allocations) --------
__device__ unsigned g_bits1[BATCH][NPTS];
__device__ unsigned g_bits2[BATCH][NPTS];
__device__ float g_cent[BATCH][KC][3];
__device__ float g_sums3[3][BATCH][KC][4];   // triple-buffered xyz sums + count

// -------- packed f32x2 helpers --------
__device__ __forceinline__ unsigned long long pk2(float lo, float hi) {
    unsigned long long r;
    asm("mov.b64 %0, {%1, %2};" : "=l"(r) : "f"(lo), "f"(hi));
    return r;
}
__device__ __forceinline__ void upk2(unsigned long long v, float& lo, float& hi) {
    asm("mov.b64 {%0, %1}, %2;" : "=f"(lo), "=f"(hi) : "l"(v));
}
__device__ __forceinline__ unsigned long long add2(unsigned long long a, unsigned long long b) {
    unsigned long long r;
    asm("add.rn.f32x2 %0, %1, %2;" : "=l"(r) : "l"(a), "l"(b));
    return r;
}
__device__ __forceinline__ unsigned long long fma2(unsigned long long a, unsigned long long b,
                                                   unsigned long long c) {
    unsigned long long r;
    asm("fma.rn.f32x2 %0, %1, %2, %3;" : "=l"(r) : "l"(a), "l"(b), "l"(c));
    return r;
}

// -------- threefry2x32 (exact JAX algorithm) --------
__device__ __forceinline__ unsigned rotl32(unsigned v, int r) {
    return (v << r) | (v >> (32 - r));
}

__device__ __forceinline__ void tf2x32(unsigned k0, unsigned k1,
                                       unsigned x0, unsigned x1,
                                       unsigned& o0, unsigned& o1) {
    unsigned k2 = k0 ^ k1 ^ 0x1BD11BDAu;
    x0 += k0; x1 += k1;
#define TFR(r) { x0 += x1; x1 = rotl32(x1, r); x1 ^= x0; }
    TFR(13) TFR(15) TFR(26) TFR(6)
    x0 += k1; x1 += k2 + 1u;
    TFR(17) TFR(29) TFR(16) TFR(24)
    x0 += k2; x1 += k0 + 2u;
    TFR(13) TFR(15) TFR(26) TFR(6)
    x0 += k0; x1 += k1 + 3u;
    TFR(17) TFR(29) TFR(16) TFR(24)
    x0 += k1; x1 += k2 + 4u;
    TFR(13) TFR(15) TFR(26) TFR(6)
    x0 += k2; x1 += k0 + 5u;
#undef TFR
    o0 = x0; o1 = x1;
}

// -------- bit generation (jax_threefry_partitionable=True semantics) --------
__global__ void gen_bits_kernel() {
    int b = blockIdx.y;
    __shared__ unsigned sk[4];
    if (threadIdx.x == 0) {
        unsigned kb0, kb1, k10, k11, s10, s11, s20, s21;
        tf2x32(0u, 42u, 0u, (unsigned)b, kb0, kb1);   // key_b
        tf2x32(kb0, kb1, 0u, 0u, k10, k11);           // key1 (carry)
        tf2x32(kb0, kb1, 0u, 1u, s10, s11);           // sub1
        tf2x32(k10, k11, 0u, 1u, s20, s21);           // sub2
        sk[0] = s10; sk[1] = s11; sk[2] = s20; sk[3] = s21;
    }
    __syncthreads();
    int j = blockIdx.x * blockDim.x + threadIdx.x;
    if (j < NPTS) {
        unsigned o0, o1;
        tf2x32(sk[0], sk[1], 0u, (unsigned)j, o0, o1);
        g_bits1[b][j] = o0 ^ o1;                       // XOR of counter-half outputs
        tf2x32(sk[2], sk[3], 0u, (unsigned)j, o0, o1);
        g_bits2[b][j] = o0 ^ o1;
    }
}

// -------- stable order-statistic selection --------
struct SelSh {
    unsigned hist[4096];
    unsigned wsum[32];
    unsigned long long lists[KC][CAP];
    unsigned listCnt[KC];
    int tb[KC];
    unsigned wr[KC];
    int ranks[KC];
    int outIdx[KC];
    int canon[KC];
    signed char binmap[4096];    // -1 or canonical list id for target bins
};

__device__ void select_ranks(const unsigned* __restrict__ keys, SelSh& sh) {
    int t = threadIdx.x;          // 1024 threads
    int lane = t & 31, wid = t >> 5;

    for (int i = t; i < 4096; i += 1024) sh.hist[i] = 0u;
    if (t < KC) sh.listCnt[t] = 0u;
    __syncthreads();

    const uint4* k4 = (const uint4*)keys;
    for (int i = t; i < NPTS / 4; i += 1024) {
        uint4 v = k4[i];
        atomicAdd(&sh.hist[v.x >> 20], 1u);
        atomicAdd(&sh.hist[v.y >> 20], 1u);
        atomicAdd(&sh.hist[v.z >> 20], 1u);
        atomicAdd(&sh.hist[v.w >> 20], 1u);
    }
    __syncthreads();

    unsigned v0 = sh.hist[4*t], v1 = sh.hist[4*t+1], v2 = sh.hist[4*t+2], v3 = sh.hist[4*t+3];
    unsigned tot = v0 + v1 + v2 + v3;
    unsigned inc = tot;
    #pragma unroll
    for (int d = 1; d < 32; d <<= 1) {
        unsigned n = __shfl_up_sync(0xffffffffu, inc, d);
        if (lane >= d) inc += n;
    }
    if (lane == 31) sh.wsum[wid] = inc;
    __syncthreads();
    if (wid == 0) {
        unsigned w = sh.wsum[lane];
        unsigned winc = w;
        #pragma unroll
        for (int d = 1; d < 32; d <<= 1) {
            unsigned n = __shfl_up_sync(0xffffffffu, winc, d);
            if (lane >= d) winc += n;
        }
        sh.wsum[lane] = winc - w;
    }
    __syncthreads();
    unsigned base = sh.wsum[wid] + (inc - tot);
    sh.hist[4*t]   = base;
    sh.hist[4*t+1] = base + v0;
    sh.hist[4*t+2] = base + v0 + v1;
    sh.hist[4*t+3] = base + v0 + v1 + v2;
    __syncthreads();

    if (t < KC) {
        unsigned r = (unsigned)sh.ranks[t];
        int lo = 0, hi = 4095;
        while (lo < hi) {
            int mid = (lo + hi + 1) >> 1;
            if (sh.hist[mid] <= r) lo = mid; else hi = mid - 1;
        }
        sh.tb[t] = lo;
        sh.wr[t] = r - sh.hist[lo];
    }
    // init binmap while tb is being computed by the first 16 threads
    for (int i = t; i < 4096; i += 1024) sh.binmap[i] = (signed char)-1;
    __syncthreads();

    if (t < KC) {
        int c = t;
        for (int j = 0; j < KC; j++) {
            if (sh.tb[j] == sh.tb[t]) { c = j; break; }   // first rank owning this bin
        }
        sh.canon[t] = c;
        if (c == t) sh.binmap[sh.tb[t]] = (signed char)t;
    }
    __syncthreads();

    for (int i = t; i < NPTS / 4; i += 1024) {
        uint4 v = k4[i];
        unsigned ks[4] = {v.x, v.y, v.z, v.w};
        #pragma unroll
        for (int s = 0; s < 4; s++) {
            int c = sh.binmap[ks[s] >> 20];
            if (c >= 0) {
                unsigned p = atomicAdd(&sh.listCnt[c], 1u);
                if (p < CAP)
                    sh.lists[c][p] = ((unsigned long long)ks[s] << 32) | (unsigned)(4*i + s);
            }
        }
    }
    __syncthreads();

    if (t < KC && sh.canon[t] == t) {
        int n = min((int)sh.listCnt[t], CAP);
        for (int a = 1; a < n; a++) {
            unsigned long long v = sh.lists[t][a];
            int q = a - 1;
            while (q >= 0 && sh.lists[t][q] > v) { sh.lists[t][q+1] = sh.lists[t][q]; q--; }
            sh.lists[t][q+1] = v;
        }
    }
    __syncthreads();
    if (t < KC) {
        int c = sh.canon[t];
        sh.outIdx[t] = (int)(sh.lists[c][sh.wr[t]] & 0xFFFFFFFFull);
    }
    __syncthreads();
}

__global__ __launch_bounds__(1024) void select_kernel(const float* __restrict__ x) {
    __shared__ SelSh sh;
    int b = blockIdx.x;
    int t = threadIdx.x;

    if (t < KC) sh.ranks[t] = t;
    __syncthreads();
    select_ranks(g_bits2[b], sh);

    if (t < KC) sh.ranks[t] = sh.outIdx[t];
    __syncthreads();
    select_ranks(g_bits1[b], sh);

    if (t < 48) {
        int k = t / 3, c = t % 3;
        int idx = sh.outIdx[k];
        g_cent[b][k][c] = x[(size_t)b * NPTS * 3 + (size_t)idx * 3 + c];
    }
    // zero accumulation buffers 0 and 1 (launch it=0 accumulates into 0, it=1 into 1)
    if (t < 64)  ((float*)g_sums3[0][b])[t] = 0.f;
    else if (t < 128) ((float*)g_sums3[1][b])[t - 64] = 0.f;
}

// -------- fused Lloyd iteration (assign + accumulate + implicit update) --------
#define NGRP 12544          // NPTS / 4 point-groups per batch
#define BLKX 11             // 11*64=704 blocks: SINGLE wave at 5 blocks/SM (740 capacity)
#define GRP_PER_BLK 1141    // ceil(12544 / 11)
#define TPB 128
#define BIG 262144.0f       // 2^18 > max ||x||^2 = 195075 -> scores strictly positive

__global__ __launch_bounds__(TPB, 5) void accum_kernel(const float* __restrict__ x, int it) {
    int b = blockIdx.y;
    int tid = threadIdx.x;
    int lane = tid & 31, wid = tid >> 5;   // wid in [0,4)

    __shared__ float sc[KC][3];
    // THREAD-PRIVATE accumulator columns: [k][j][wid][lane] — each (wid,lane)=thread
    // owns its column; no cross-thread RMW. j: 0=(x0,x1), 1=(x2,cnt).  32 KB.
    __shared__ unsigned long long sacc[KC][2][4][32];

    if (tid < 48) {
        int k = tid / 3, c = tid % 3;
        if (it == 0) {
            sc[k][c] = g_cent[b][k][c];
        } else {
            const float* pb = (const float*)g_sums3[(it + 2) % 3][b];
            sc[k][c] = pb[k * 4 + c] / pb[k * 4 + 3];
        }
    }
    // zero the buffer the NEXT launch will accumulate into
    if (blockIdx.x == 0 && tid >= 64 && tid < 128)
        ((float*)g_sums3[(it + 1) % 3][b])[tid - 64] = 0.f;
    // zero smem accumulators: 4096 ull / 128 threads = 32 each
    {
        unsigned long long* p = &sacc[0][0][0][0];
        #pragma unroll
        for (int i = 0; i < 32; i++) p[tid + TPB * i] = 0ull;
    }
    __syncthreads();

    // dot-form weights, packed per cluster pair, in registers:
    // score_k(x) = x·(-2 c_k) + ||c_k||^2 + BIG   (argmin score == argmin (x-c)^2;
    // BIG keeps scores strictly positive so float ordering == int ordering)
    unsigned long long wx[KC/2], wy[KC/2], wz[KC/2], wb[KC/2];
    #pragma unroll
    for (int p = 0; p < KC/2; p++) {
        float c0lo = sc[2*p][0],   c1lo = sc[2*p][1],   c2lo = sc[2*p][2];
        float c0hi = sc[2*p+1][0], c1hi = sc[2*p+1][1], c2hi = sc[2*p+1][2];
        wx[p] = pk2(-2.f * c0lo, -2.f * c0hi);
        wy[p] = pk2(-2.f * c1lo, -2.f * c1hi);
        wz[p] = pk2(-2.f * c2lo, -2.f * c2hi);
        wb[p] = pk2(c0lo*c0lo + c1lo*c1lo + c2lo*c2lo + BIG,
                    c0hi*c0hi + c1hi*c1hi + c2hi*c2hi + BIG);
    }

    const float4* xb4 = (const float4*)(x + (size_t)b * NPTS * 3);
    int gbeg = blockIdx.x * GRP_PER_BLK;
    int gend = min(gbeg + GRP_PER_BLK, NGRP);

    for (int g = gbeg + tid; g < gend; g += TPB) {
        float4 A = xb4[3*g], Bv = xb4[3*g + 1], Cv = xb4[3*g + 2];
        float px[4], py[4], pz[4];
        px[0] = A.x;  py[0] = A.y;  pz[0] = A.z;
        px[1] = A.w;  py[1] = Bv.x; pz[1] = Bv.y;
        px[2] = Bv.z; py[2] = Bv.w; pz[2] = Cv.x;
        px[3] = Cv.y; py[3] = Cv.z; pz[3] = Cv.w;

        #pragma unroll
        for (int q = 0; q < 4; q++) {
            float x0 = px[q], x1 = py[q], x2 = pz[q];
            unsigned long long x00 = pk2(x0, x0);
            unsigned long long x11 = pk2(x1, x1);
            unsigned long long x22 = pk2(x2, x2);

            // masked-int argmin: positive-float bits order as ints; low 4 bits carry k.
            int best = 0x7FFFFFFF;
            #pragma unroll
            for (int p = 0; p < KC/2; p++) {
                unsigned long long s = fma2(x00, wx[p],
                                       fma2(x11, wy[p],
                                       fma2(x22, wz[p], wb[p])));
                float slo, shi;
                upk2(s, slo, shi);
                int ulo = (__float_as_int(slo) & ~15) | (2*p);
                int uhi = (__float_as_int(shi) & ~15) | (2*p + 1);
                best = min(best, ulo);
                best = min(best, uhi);
            }
            int bk = best & 15;

            unsigned long long* a01 = &sacc[bk][0][wid][lane];
            unsigned long long* a23 = &sacc[bk][1][wid][lane];
            *a01 = add2(*a01, pk2(x0, x1));
            *a23 = add2(*a23, pk2(x2, 1.0f));
        }
    }

    __syncthreads();

    // reduce: 32 packed outputs [k][j]; each warp handles 8.
    // v = sum over the 4 wid-copies at this lane, then warp shfl-reduce.
    #pragma unroll
    for (int o = 0; o < 8; o++) {
        int idx = wid * 8 + o;            // 0..31
        int k = idx >> 1, j = idx & 1;
        unsigned long long v = add2(add2(sacc[k][j][0][lane], sacc[k][j][1][lane]),
                                    add2(sacc[k][j][2][lane], sacc[k][j][3][lane]));
        #pragma unroll
        for (int off = 16; off > 0; off >>= 1)
            v = add2(v, __shfl_down_sync(0xffffffffu, v, off));
        if (lane == 0) {
            float vlo, vhi;
            upk2(v, vlo, vhi);
            float* gp = (float*)g_sums3[it % 3][b];
            atomicAdd(&gp[k * 4 + j * 2 + 0], vlo);
            atomicAdd(&gp[k * 4 + j * 2 + 1], vhi);
        }
    }
}

__global__ void finalize_kernel(float* __restrict__ out) {
    int b = blockIdx.x, t = threadIdx.x;   // 64 threads; last sums in buffer 9%3 == 0
    if (t < 48) {
        int k = t / 3, c = t % 3;
        const float* pb = (const float*)g_sums3[0][b];
        out[b * 48 + t] = pb[k * 4 + c] / pb[k * 4 + 3];
    }
}

// -------- launch --------
extern "C" void kernel_launch(void* const* d_in, const int* in_sizes, int n_in,
                              void* d_out, int out_size) {
    const float* x = (const float*)d_in[0];
    float* out = (float*)d_out;

    gen_bits_kernel<<<dim3(196, BATCH), 256>>>();   // 196*256 = 50176 = NPTS
    select_kernel<<<BATCH, 1024>>>(x);
    for (int it = 0; it < 10; it++) {
        accum_kernel<<<dim3(BLKX, BATCH), TPB>>>(x, it);
    }
    finalize_kernel<<<BATCH, 64>>>(out);
}

// round 17
// speedup vs baseline: 1.0509x; 1.0509x over previous
#include <cuda_runtime.h>

#define NPTS 50176
#define BATCH 64
#define KC 16
#define CAP 192

// -------- scratch (static device memory; no allocations) --------
__device__ unsigned g_bits1[BATCH][NPTS];
__device__ unsigned g_bits2[BATCH][NPTS];
__device__ float g_cent[BATCH][KC][3];
__device__ float g_sums3[3][BATCH][KC][4];   // triple-buffered xyz sums + count

// -------- packed f32x2 helpers --------
__device__ __forceinline__ unsigned long long pk2(float lo, float hi) {
    unsigned long long r;
    asm("mov.b64 %0, {%1, %2};" : "=l"(r) : "f"(lo), "f"(hi));
    return r;
}
__device__ __forceinline__ void upk2(unsigned long long v, float& lo, float& hi) {
    asm("mov.b64 {%0, %1}, %2;" : "=f"(lo), "=f"(hi) : "l"(v));
}
__device__ __forceinline__ unsigned long long add2(unsigned long long a, unsigned long long b) {
    unsigned long long r;
    asm("add.rn.f32x2 %0, %1, %2;" : "=l"(r) : "l"(a), "l"(b));
    return r;
}
__device__ __forceinline__ unsigned long long fma2(unsigned long long a, unsigned long long b,
                                                   unsigned long long c) {
    unsigned long long r;
    asm("fma.rn.f32x2 %0, %1, %2, %3;" : "=l"(r) : "l"(a), "l"(b), "l"(c));
    return r;
}

// -------- threefry2x32 (exact JAX algorithm) --------
__device__ __forceinline__ unsigned rotl32(unsigned v, int r) {
    return (v << r) | (v >> (32 - r));
}

__device__ __forceinline__ void tf2x32(unsigned k0, unsigned k1,
                                       unsigned x0, unsigned x1,
                                       unsigned& o0, unsigned& o1) {
    unsigned k2 = k0 ^ k1 ^ 0x1BD11BDAu;
    x0 += k0; x1 += k1;
#define TFR(r) { x0 += x1; x1 = rotl32(x1, r); x1 ^= x0; }
    TFR(13) TFR(15) TFR(26) TFR(6)
    x0 += k1; x1 += k2 + 1u;
    TFR(17) TFR(29) TFR(16) TFR(24)
    x0 += k2; x1 += k0 + 2u;
    TFR(13) TFR(15) TFR(26) TFR(6)
    x0 += k0; x1 += k1 + 3u;
    TFR(17) TFR(29) TFR(16) TFR(24)
    x0 += k1; x1 += k2 + 4u;
    TFR(13) TFR(15) TFR(26) TFR(6)
    x0 += k2; x1 += k0 + 5u;
#undef TFR
    o0 = x0; o1 = x1;
}

// -------- bit generation (jax_threefry_partitionable=True semantics) --------
__global__ void gen_bits_kernel() {
    int b = blockIdx.y;
    __shared__ unsigned sk[4];
    if (threadIdx.x == 0) {
        unsigned kb0, kb1, k10, k11, s10, s11, s20, s21;
        tf2x32(0u, 42u, 0u, (unsigned)b, kb0, kb1);   // key_b
        tf2x32(kb0, kb1, 0u, 0u, k10, k11);           // key1 (carry)
        tf2x32(kb0, kb1, 0u, 1u, s10, s11);           // sub1
        tf2x32(k10, k11, 0u, 1u, s20, s21);           // sub2
        sk[0] = s10; sk[1] = s11; sk[2] = s20; sk[3] = s21;
    }
    __syncthreads();
    int j = blockIdx.x * blockDim.x + threadIdx.x;
    if (j < NPTS) {
        unsigned o0, o1;
        tf2x32(sk[0], sk[1], 0u, (unsigned)j, o0, o1);
        g_bits1[b][j] = o0 ^ o1;                       // XOR of counter-half outputs
        tf2x32(sk[2], sk[3], 0u, (unsigned)j, o0, o1);
        g_bits2[b][j] = o0 ^ o1;
    }
}

// -------- stable order-statistic selection --------
struct SelSh {
    unsigned hist[4096];
    unsigned wsum[32];
    unsigned long long lists[KC][CAP];
    unsigned listCnt[KC];
    int tb[KC];
    unsigned wr[KC];
    int ranks[KC];
    int outIdx[KC];
    int canon[KC];
    signed char binmap[4096];    // -1 or canonical list id for target bins
};

__device__ void select_ranks(const unsigned* __restrict__ keys, SelSh& sh) {
    int t = threadIdx.x;          // 1024 threads
    int lane = t & 31, wid = t >> 5;

    for (int i = t; i < 4096; i += 1024) sh.hist[i] = 0u;
    if (t < KC) sh.listCnt[t] = 0u;
    __syncthreads();

    const uint4* k4 = (const uint4*)keys;
    for (int i = t; i < NPTS / 4; i += 1024) {
        uint4 v = k4[i];
        atomicAdd(&sh.hist[v.x >> 20], 1u);
        atomicAdd(&sh.hist[v.y >> 20], 1u);
        atomicAdd(&sh.hist[v.z >> 20], 1u);
        atomicAdd(&sh.hist[v.w >> 20], 1u);
    }
    __syncthreads();

    unsigned v0 = sh.hist[4*t], v1 = sh.hist[4*t+1], v2 = sh.hist[4*t+2], v3 = sh.hist[4*t+3];
    unsigned tot = v0 + v1 + v2 + v3;
    unsigned inc = tot;
    #pragma unroll
    for (int d = 1; d < 32; d <<= 1) {
        unsigned n = __shfl_up_sync(0xffffffffu, inc, d);
        if (lane >= d) inc += n;
    }
    if (lane == 31) sh.wsum[wid] = inc;
    __syncthreads();
    if (wid == 0) {
        unsigned w = sh.wsum[lane];
        unsigned winc = w;
        #pragma unroll
        for (int d = 1; d < 32; d <<= 1) {
            unsigned n = __shfl_up_sync(0xffffffffu, winc, d);
            if (lane >= d) winc += n;
        }
        sh.wsum[lane] = winc - w;
    }
    __syncthreads();
    unsigned base = sh.wsum[wid] + (inc - tot);
    sh.hist[4*t]   = base;
    sh.hist[4*t+1] = base + v0;
    sh.hist[4*t+2] = base + v0 + v1;
    sh.hist[4*t+3] = base + v0 + v1 + v2;
    __syncthreads();

    if (t < KC) {
        unsigned r = (unsigned)sh.ranks[t];
        int lo = 0, hi = 4095;
        while (lo < hi) {
            int mid = (lo + hi + 1) >> 1;
            if (sh.hist[mid] <= r) lo = mid; else hi = mid - 1;
        }
        sh.tb[t] = lo;
        sh.wr[t] = r - sh.hist[lo];
    }
    // init binmap while tb is being computed by the first 16 threads
    for (int i = t; i < 4096; i += 1024) sh.binmap[i] = (signed char)-1;
    __syncthreads();

    if (t < KC) {
        int c = t;
        for (int j = 0; j < KC; j++) {
            if (sh.tb[j] == sh.tb[t]) { c = j; break; }   // first rank owning this bin
        }
        sh.canon[t] = c;
        if (c == t) sh.binmap[sh.tb[t]] = (signed char)t;
    }
    __syncthreads();

    for (int i = t; i < NPTS / 4; i += 1024) {
        uint4 v = k4[i];
        unsigned ks[4] = {v.x, v.y, v.z, v.w};
        #pragma unroll
        for (int s = 0; s < 4; s++) {
            int c = sh.binmap[ks[s] >> 20];
            if (c >= 0) {
                unsigned p = atomicAdd(&sh.listCnt[c], 1u);
                if (p < CAP)
                    sh.lists[c][p] = ((unsigned long long)ks[s] << 32) | (unsigned)(4*i + s);
            }
        }
    }
    __syncthreads();

    if (t < KC && sh.canon[t] == t) {
        int n = min((int)sh.listCnt[t], CAP);
        for (int a = 1; a < n; a++) {
            unsigned long long v = sh.lists[t][a];
            int q = a - 1;
            while (q >= 0 && sh.lists[t][q] > v) { sh.lists[t][q+1] = sh.lists[t][q]; q--; }
            sh.lists[t][q+1] = v;
        }
    }
    __syncthreads();
    if (t < KC) {
        int c = sh.canon[t];
        sh.outIdx[t] = (int)(sh.lists[c][sh.wr[t]] & 0xFFFFFFFFull);
    }
    __syncthreads();
}

__global__ __launch_bounds__(1024) void select_kernel(const float* __restrict__ x) {
    __shared__ SelSh sh;
    int b = blockIdx.x;
    int t = threadIdx.x;

    if (t < KC) sh.ranks[t] = t;
    __syncthreads();
    select_ranks(g_bits2[b], sh);

    if (t < KC) sh.ranks[t] = sh.outIdx[t];
    __syncthreads();
    select_ranks(g_bits1[b], sh);

    if (t < 48) {
        int k = t / 3, c = t % 3;
        int idx = sh.outIdx[k];
        g_cent[b][k][c] = x[(size_t)b * NPTS * 3 + (size_t)idx * 3 + c];
    }
    // zero accumulation buffers 0 and 1 (launch it=0 accumulates into 0, it=1 into 1)
    if (t < 64)  ((float*)g_sums3[0][b])[t] = 0.f;
    else if (t < 128) ((float*)g_sums3[1][b])[t - 64] = 0.f;
}

// -------- fused Lloyd iteration (assign + accumulate + implicit update) --------
#define NGRP 12544          // NPTS / 4 point-groups per batch
#define BLKX 11             // 11*64=704 blocks: SINGLE wave at 5 blocks/SM (740 capacity)
#define GRP_PER_BLK 1141    // ceil(12544 / 11)
#define TPB 128
#define BIG 262144.0f       // 2^18 > max ||x||^2 = 195075 -> scores strictly positive

__global__ __launch_bounds__(TPB, 5) void accum_kernel(const float* __restrict__ x, int it) {
    int b = blockIdx.y;
    int tid = threadIdx.x;
    int lane = tid & 31, wid = tid >> 5;   // wid in [0,4)

    __shared__ float sc[KC][3];
    // THREAD-PRIVATE accumulator columns: [k][j][wid][lane] — each (wid,lane)=thread
    // owns its column; no cross-thread RMW. j: 0=(x0,x1), 1=(x2,cnt).  32 KB.
    __shared__ unsigned long long sacc[KC][2][4][32];

    if (tid < 48) {
        int k = tid / 3, c = tid % 3;
        if (it == 0) {
            sc[k][c] = g_cent[b][k][c];
        } else {
            const float* pb = (const float*)g_sums3[(it + 2) % 3][b];
            sc[k][c] = pb[k * 4 + c] / pb[k * 4 + 3];
        }
    }
    // zero the buffer the NEXT launch will accumulate into
    if (blockIdx.x == 0 && tid >= 64 && tid < 128)
        ((float*)g_sums3[(it + 1) % 3][b])[tid - 64] = 0.f;
    // zero smem accumulators: 4096 ull / 128 threads = 32 each
    {
        unsigned long long* p = &sacc[0][0][0][0];
        #pragma unroll
        for (int i = 0; i < 32; i++) p[tid + TPB * i] = 0ull;
    }
    __syncthreads();

    // dot-form weights, packed per cluster pair, in registers:
    // score_k(x) = x·(-2 c_k) + ||c_k||^2 + BIG   (argmin score == argmin (x-c)^2;
    // BIG keeps scores strictly positive so float ordering == int ordering)
    unsigned long long wx[KC/2], wy[KC/2], wz[KC/2], wb[KC/2];
    #pragma unroll
    for (int p = 0; p < KC/2; p++) {
        float c0lo = sc[2*p][0],   c1lo = sc[2*p][1],   c2lo = sc[2*p][2];
        float c0hi = sc[2*p+1][0], c1hi = sc[2*p+1][1], c2hi = sc[2*p+1][2];
        wx[p] = pk2(-2.f * c0lo, -2.f * c0hi);
        wy[p] = pk2(-2.f * c1lo, -2.f * c1hi);
        wz[p] = pk2(-2.f * c2lo, -2.f * c2hi);
        wb[p] = pk2(c0lo*c0lo + c1lo*c1lo + c2lo*c2lo + BIG,
                    c0hi*c0hi + c1hi*c1hi + c2hi*c2hi + BIG);
    }

    const float4* xb4 = (const float4*)(x + (size_t)b * NPTS * 3);
    int gbeg = blockIdx.x * GRP_PER_BLK;
    int gend = min(gbeg + GRP_PER_BLK, NGRP);

    for (int g = gbeg + tid; g < gend; g += TPB) {
        float4 A = xb4[3*g], Bv = xb4[3*g + 1], Cv = xb4[3*g + 2];

        // one point: balanced-tree masked-int argmin (depth 4, not a 16-deep chain)
        #define DO_POINT(x0, x1, x2)                                              \
        {                                                                         \
            float _x0 = (x0), _x1 = (x1), _x2 = (x2);                             \
            unsigned long long x00 = pk2(_x0, _x0);                               \
            unsigned long long x11 = pk2(_x1, _x1);                               \
            unsigned long long x22 = pk2(_x2, _x2);                               \
            int u[KC];                                                            \
            _Pragma("unroll")                                                     \
            for (int p = 0; p < KC/2; p++) {                                      \
                unsigned long long s = fma2(x00, wx[p],                           \
                                       fma2(x11, wy[p],                           \
                                       fma2(x22, wz[p], wb[p])));                 \
                float slo, shi;                                                   \
                upk2(s, slo, shi);                                                \
                u[2*p]   = (__float_as_int(slo) & ~15) | (2*p);                   \
                u[2*p+1] = (__float_as_int(shi) & ~15) | (2*p + 1);               \
            }                                                                     \
            _Pragma("unroll")                                                     \
            for (int st = 1; st < KC; st <<= 1) {                                 \
                _Pragma("unroll")                                                 \
                for (int i = 0; i < KC; i += 2*st)                                \
                    u[i] = min(u[i], u[i + st]);                                  \
            }                                                                     \
            int bk = u[0] & 15;                                                   \
            unsigned long long* a01 = &sacc[bk][0][wid][lane];                    \
            unsigned long long* a23 = &sacc[bk][1][wid][lane];                    \
            *a01 = add2(*a01, pk2(_x0, _x1));                                     \
            *a23 = add2(*a23, pk2(_x2, 1.0f));                                    \
        }

        DO_POINT(A.x,  A.y,  A.z)
        DO_POINT(A.w,  Bv.x, Bv.y)
        DO_POINT(Bv.z, Bv.w, Cv.x)
        DO_POINT(Cv.y, Cv.z, Cv.w)
        #undef DO_POINT
    }

    __syncthreads();

    // reduce: 32 packed outputs [k][j]; each warp handles 8.
    // v = sum over the 4 wid-copies at this lane, then warp shfl-reduce.
    #pragma unroll
    for (int o = 0; o < 8; o++) {
        int idx = wid * 8 + o;            // 0..31
        int k = idx >> 1, j = idx & 1;
        unsigned long long v = add2(add2(sacc[k][j][0][lane], sacc[k][j][1][lane]),
                                    add2(sacc[k][j][2][lane], sacc[k][j][3][lane]));
        #pragma unroll
        for (int off = 16; off > 0; off >>= 1)
            v = add2(v, __shfl_down_sync(0xffffffffu, v, off));
        if (lane == 0) {
            float vlo, vhi;
            upk2(v, vlo, vhi);
            float* gp = (float*)g_sums3[it % 3][b];
            atomicAdd(&gp[k * 4 + j * 2 + 0], vlo);
            atomicAdd(&gp[k * 4 + j * 2 + 1], vhi);
        }
    }
}

__global__ void finalize_kernel(float* __restrict__ out) {
    int b = blockIdx.x, t = threadIdx.x;   // 64 threads; last sums in buffer 9%3 == 0
    if (t < 48) {
        int k = t / 3, c = t % 3;
        const float* pb = (const float*)g_sums3[0][b];
        out[b * 48 + t] = pb[k * 4 + c] / pb[k * 4 + 3];
    }
}

// -------- launch --------
extern "C" void kernel_launch(void* const* d_in, const int* in_sizes, int n_in,
                              void* d_out, int out_size) {
    const float* x = (const float*)d_in[0];
    float* out = (float*)d_out;

    gen_bits_kernel<<<dim3(196, BATCH), 256>>>();   // 196*256 = 50176 = NPTS
    select_kernel<<<BATCH, 1024>>>(x);
    for (int it = 0; it < 10; it++) {
        accum_kernel<<<dim3(BLKX, BATCH), TPB>>>(x, it);
    }
    finalize_kernel<<<BATCH, 64>>>(out);
}